// round 3
// baseline (speedup 1.0000x reference)
#include <cuda_runtime.h>
#include <cstdint>

#define NB 32
#define NM 2048
#define ND 1024

#define TM 128
#define TH 128
#define KC 32
#define ASTR 132   // smem row stride (floats), multiple of 4 for aligned float4 reads

// scratch (static device globals; no allocations allowed)
__device__ float g_qp[NB * ND];
__device__ float g_ctx[NB * ND];

// ---------------- dtype-robust memory_lengths loader ----------------------
// Reference requests int64 but JAX without x64 materializes int32. Lengths are
// in [1, 2048] (never 0), so for an int64 little-endian array every odd 32-bit
// word is 0. Probe a few odd words to detect the layout.
__device__ __forceinline__ int load_len(const int* __restrict__ L, int b) {
    bool is64 = (L[1] == 0) && (L[3] == 0) && (L[5] == 0);
    return is64 ? L[2 * b] : L[b];
}

// ---------------- packed f32x2 helpers (full-rate fp32 on sm_103a) --------
__device__ __forceinline__ unsigned long long pack2(float x, float y) {
    unsigned long long r;
    asm("mov.b64 %0, {%1, %2};" : "=l"(r) : "f"(x), "f"(y));
    return r;
}
__device__ __forceinline__ void fma2(unsigned long long& d,
                                     unsigned long long a, unsigned long long b) {
    asm("fma.rn.f32x2 %0, %1, %2, %0;" : "+l"(d) : "l"(a), "l"(b));
}
__device__ __forceinline__ void unpack2(unsigned long long v, float& lo, float& hi) {
    asm("mov.b64 {%0, %1}, %2;" : "=f"(lo), "=f"(hi) : "l"(v));
}
__device__ __forceinline__ float tanh_fast(float x) {
    float r;
    asm("tanh.approx.f32 %0, %1;" : "=f"(r) : "f"(x));
    return r;
}

// ---------------- Kernel 1: q_proj[b,h] = queries[b,:] . W_query[h,:] -----
__global__ void qproj_kernel(const float* __restrict__ q,
                             const float* __restrict__ Wq) {
    int b = blockIdx.y;
    int h = blockIdx.x * 8 + (threadIdx.x >> 5);
    int lane = threadIdx.x & 31;
    const float* qr = q + (size_t)b * ND;
    const float* wr = Wq + (size_t)h * ND;
    float acc = 0.f;
    #pragma unroll 8
    for (int d = lane; d < ND; d += 32) acc += qr[d] * wr[d];
    #pragma unroll
    for (int o = 16; o; o >>= 1) acc += __shfl_down_sync(0xffffffffu, acc, o);
    if (lane == 0) g_qp[b * ND + h] = acc;
}

// ---------------- Kernel 2: fused score GEMM -----------------------------
// scores[b,m] = sum_h W_energy[h] * tanh( qp[b,h] + sum_d keys[b,m,d]*W_key[h,d] )
__global__ __launch_bounds__(256)
void score_kernel(const float* __restrict__ keys,
                  const float* __restrict__ Wk,
                  const float* __restrict__ We,
                  const int* __restrict__ lens,
                  float* __restrict__ attn_out) {
    int b = blockIdx.y;
    int m0 = blockIdx.x * TM;
    int len = load_len(lens, b);
    if (m0 >= len) return;   // fully-masked tile: skip

    __shared__ float As[KC][ASTR];  // keys tile, transposed  [d][m]
    __shared__ float Bs[KC][ASTR];  // W_key tile, transposed [d][h]

    int tid = threadIdx.x;
    int tx = tid & 15;       // h sub-tile
    int ty = tid >> 4;       // m sub-tile

    const float* keysB = keys + (size_t)b * NM * ND;

    float spart[8];
    #pragma unroll
    for (int i = 0; i < 8; ++i) spart[i] = 0.f;

    for (int hc = 0; hc < ND / TH; ++hc) {
        int h0 = hc * TH;
        unsigned long long acc2[8][4];
        #pragma unroll
        for (int i = 0; i < 8; ++i)
            #pragma unroll
            for (int p = 0; p < 4; ++p) acc2[i][p] = 0ull;

        for (int kt = 0; kt < ND / KC; ++kt) {
            __syncthreads();
            // cooperative load of both tiles (coalesced 128B rows)
            #pragma unroll
            for (int l = 0; l < 4; ++l) {
                int idx = l * 256 + tid;
                int r = idx >> 3;           // row within tile (0..127)
                int dd = (idx & 7) << 2;    // d offset within K-chunk
                float4 va = *(const float4*)(keysB + (size_t)(m0 + r) * ND + kt * KC + dd);
                As[dd + 0][r] = va.x; As[dd + 1][r] = va.y;
                As[dd + 2][r] = va.z; As[dd + 3][r] = va.w;
                float4 vb = *(const float4*)(Wk + (size_t)(h0 + r) * ND + kt * KC + dd);
                Bs[dd + 0][r] = vb.x; Bs[dd + 1][r] = vb.y;
                Bs[dd + 2][r] = vb.z; Bs[dd + 3][r] = vb.w;
            }
            __syncthreads();

            #pragma unroll
            for (int k = 0; k < KC; ++k) {
                float4 a0 = *(const float4*)&As[k][ty * 4];
                float4 a1 = *(const float4*)&As[k][64 + ty * 4];
                float4 b0 = *(const float4*)&Bs[k][tx * 4];
                float4 b1 = *(const float4*)&Bs[k][64 + tx * 4];
                float av[8] = {a0.x, a0.y, a0.z, a0.w, a1.x, a1.y, a1.z, a1.w};
                unsigned long long bb[4];
                bb[0] = pack2(b0.x, b0.y);
                bb[1] = pack2(b0.z, b0.w);
                bb[2] = pack2(b1.x, b1.y);
                bb[3] = pack2(b1.z, b1.w);
                #pragma unroll
                for (int i = 0; i < 8; ++i) {
                    unsigned long long aa = pack2(av[i], av[i]);
                    #pragma unroll
                    for (int p = 0; p < 4; ++p) fma2(acc2[i][p], aa, bb[p]);
                }
            }
        }

        // epilogue: tanh(qp + C) . W_energy, accumulate per-row partials
        #pragma unroll
        for (int p = 0; p < 4; ++p) {
            int c0 = h0 + ((p >> 1) << 6) + tx * 4 + ((p & 1) << 1); // first col of pair
            float we0 = We[c0],     we1 = We[c0 + 1];
            float qv0 = g_qp[b * ND + c0], qv1 = g_qp[b * ND + c0 + 1];
            #pragma unroll
            for (int i = 0; i < 8; ++i) {
                float clo, chi;
                unpack2(acc2[i][p], clo, chi);
                spart[i] += tanh_fast(clo + qv0) * we0;
                spart[i] += tanh_fast(chi + qv1) * we1;
            }
        }
    }

    // reduce partial scores across the 16 tx lanes of each row
    __syncthreads();
    float (*sred)[17] = (float(*)[17]) & As[0][0];  // 128*17 floats fits in As
    #pragma unroll
    for (int i = 0; i < 8; ++i) {
        int r = ty * 4 + (i & 3) + ((i >> 2) << 6);
        sred[r][tx] = spart[i];
    }
    __syncthreads();
    if (tid < TM) {
        float s = 0.f;
        #pragma unroll
        for (int j = 0; j < 16; ++j) s += sred[tid][j];
        attn_out[b * NM + m0 + tid] = s;
    }
}

// ---------------- Kernel 3: masked softmax over scores (in-place) --------
__global__ void softmax_kernel(const int* __restrict__ lens,
                               float* __restrict__ attn) {
    int b = blockIdx.x;
    int len = load_len(lens, b);
    float* row = attn + (size_t)b * NM;
    __shared__ float red[256];
    int tid = threadIdx.x;

    float mx = -3.0e38f;
    for (int m = tid; m < len; m += 256) mx = fmaxf(mx, row[m]);
    red[tid] = mx; __syncthreads();
    for (int s = 128; s; s >>= 1) {
        if (tid < s) red[tid] = fmaxf(red[tid], red[tid + s]);
        __syncthreads();
    }
    mx = red[0]; __syncthreads();

    float sm = 0.f;
    for (int m = tid; m < len; m += 256) sm += expf(row[m] - mx);
    red[tid] = sm; __syncthreads();
    for (int s = 128; s; s >>= 1) {
        if (tid < s) red[tid] += red[tid + s];
        __syncthreads();
    }
    float inv = 1.f / red[0];
    __syncthreads();

    for (int m = tid; m < NM; m += 256) {
        float w = (m < len) ? expf(row[m] - mx) * inv : 0.f;
        row[m] = w;
    }
}

// ---------------- Kernel 4: ctx[b,d] = sum_{m<len} attn[b,m]*values[b,m,d]
__global__ void ctx_kernel(const float* __restrict__ values,
                           const int* __restrict__ lens,
                           const float* __restrict__ attn) {
    int b = blockIdx.y;
    int d = blockIdx.x * 256 + threadIdx.x;
    int len = load_len(lens, b);
    __shared__ float sw[256];
    const float* vb = values + (size_t)b * NM * ND;
    float acc = 0.f;
    for (int mc = 0; mc < len; mc += 256) {
        int mm = mc + threadIdx.x;
        __syncthreads();
        sw[threadIdx.x] = (mm < len) ? attn[(size_t)b * NM + mm] : 0.f;
        __syncthreads();
        int lim = min(256, len - mc);
        #pragma unroll 4
        for (int t = 0; t < lim; ++t)
            acc += sw[t] * vb[(size_t)(mc + t) * ND + d];
    }
    g_ctx[b * ND + d] = acc;
}

// ---------------- Kernel 5: out[b,h] = ctx[b,:] . W_key[h,:] -------------
// (projected_values folded through attention:  attn@(V@Wk^T) == (attn@V)@Wk^T)
__global__ void outproj_kernel(const float* __restrict__ Wk,
                               float* __restrict__ out) {
    int b = blockIdx.y;
    int h = blockIdx.x * 8 + (threadIdx.x >> 5);
    int lane = threadIdx.x & 31;
    const float* xr = g_ctx + (size_t)b * ND;
    const float* wr = Wk + (size_t)h * ND;
    float acc = 0.f;
    #pragma unroll 8
    for (int d = lane; d < ND; d += 32) acc += xr[d] * wr[d];
    #pragma unroll
    for (int o = 16; o; o >>= 1) acc += __shfl_down_sync(0xffffffffu, acc, o);
    if (lane == 0) out[b * ND + h] = acc;
}

// ---------------- launch -------------------------------------------------
extern "C" void kernel_launch(void* const* d_in, const int* in_sizes, int n_in,
                              void* d_out, int out_size) {
    const float* queries = (const float*)d_in[0];      // [B,1,D]
    const float* keys    = (const float*)d_in[1];      // [B,M,D]
    const float* values  = (const float*)d_in[2];      // [B,M,D]
    const int*   lens    = (const int*)d_in[3];        // [B] int32 or int64
    const float* Wk      = (const float*)d_in[4];      // [D,D]
    const float* Wq      = (const float*)d_in[5];      // [D,D]
    const float* We      = (const float*)d_in[6];      // [1,D]

    float* out       = (float*)d_out;
    float* out_val   = out;             // [B,1,D]  = B*D floats
    float* out_attn  = out + NB * ND;   // [B,1,M]  = B*M floats

    qproj_kernel  <<<dim3(ND / 8, NB), 256>>>(queries, Wq);
    score_kernel  <<<dim3(NM / TM, NB), 256>>>(keys, Wk, We, lens, out_attn);
    softmax_kernel<<<NB, 256>>>(lens, out_attn);
    ctx_kernel    <<<dim3(ND / 256, NB), 256>>>(values, lens, out_attn);
    outproj_kernel<<<dim3(ND / 8, NB), 256>>>(Wk, out_val);
}

// round 7
// speedup vs baseline: 3.3377x; 3.3377x over previous
#include <cuda_runtime.h>
#include <cstdint>

#define NB 32
#define NM 2048
#define ND 1024
#define TM 128

// ---- score kernel (mma.sync tf32) tiling ----
#define A_BYTES 18432           // 128 rows * 36 floats * 4B
#define SC_SMEM (4 * A_BYTES)   // A x2 stages, B x2 stages = 73728B

// scratch
__device__ float g_qp[NB * ND];
__device__ float g_ctx[NB * ND];
__device__ float g_ctxp[NB * 8 * ND];

// ---------------- helpers ------------------------------------------------
__device__ __forceinline__ int load_len(const int* __restrict__ L, int b) {
    bool is64 = (L[1] == 0) && (L[3] == 0) && (L[5] == 0);
    return is64 ? L[2 * b] : L[b];
}
__device__ __forceinline__ float tanh_fast(float x) {
    float r; asm("tanh.approx.f32 %0, %1;" : "=f"(r) : "f"(x)); return r;
}
__device__ __forceinline__ unsigned int smem_u32(const void* p) {
    unsigned int a;
    asm("{ .reg .u64 t; cvta.to.shared.u64 t, %1; cvt.u32.u64 %0, t; }" : "=r"(a) : "l"(p));
    return a;
}
__device__ __forceinline__ void cpasync16(unsigned int dst, const float* src) {
    asm volatile("cp.async.cg.shared.global [%0], [%1], 16;" :: "r"(dst), "l"(src) : "memory");
}
__device__ __forceinline__ unsigned int to_tf32(float x) {
    unsigned int u;
    asm("cvt.rna.tf32.f32 %0, %1;" : "=r"(u) : "f"(x));
    return u;
}
__device__ __forceinline__ void mma_tf32(float d[4], const unsigned int a[4],
                                         const unsigned int b[2]) {
    asm volatile(
        "mma.sync.aligned.m16n8k8.row.col.f32.tf32.tf32.f32 "
        "{%0,%1,%2,%3}, {%4,%5,%6,%7}, {%8,%9}, {%0,%1,%2,%3};"
        : "+f"(d[0]), "+f"(d[1]), "+f"(d[2]), "+f"(d[3])
        : "r"(a[0]), "r"(a[1]), "r"(a[2]), "r"(a[3]), "r"(b[0]), "r"(b[1]));
}

// ---------------- Kernel 1: q projection ---------------------------------
__global__ void qproj_kernel(const float* __restrict__ q,
                             const float* __restrict__ Wq) {
    int b = blockIdx.y;
    int h = blockIdx.x * 8 + (threadIdx.x >> 5);
    int lane = threadIdx.x & 31;
    const float* qr = q + (size_t)b * ND;
    const float* wr = Wq + (size_t)h * ND;
    float acc = 0.f;
    #pragma unroll 8
    for (int d = lane; d < ND; d += 32) acc += qr[d] * wr[d];
    #pragma unroll
    for (int o = 16; o; o >>= 1) acc += __shfl_down_sync(0xffffffffu, acc, o);
    if (lane == 0) g_qp[b * ND + h] = acc;
}

// ---------------- Kernel 2: tf32 mma.sync score GEMM ---------------------
// scores[b,m] = sum_h We[h]*tanh(qp[b,h] + sum_d keys[b,m,d]*Wk[h,d])
// Stage s = hc*32 + kt : A tile = keys[m0:m0+128, kt*32:+32]
//                        B tile = Wk[hc*128:+128,  kt*32:+32]
__device__ __forceinline__ void load_stage(unsigned int sbase,
                                           const float* __restrict__ keysB,
                                           const float* __restrict__ Wk,
                                           int m0, int s, int tid) {
    int hc = s >> 5, kt = s & 31, bf = s & 1;
    int k0 = kt * 32;
    unsigned int abase = sbase + bf * A_BYTES;
    unsigned int bbase = sbase + 2 * A_BYTES + bf * A_BYTES;
    #pragma unroll
    for (int i = 0; i < 4; ++i) {
        int idx = i * 256 + tid;
        int r = idx >> 3, c8 = idx & 7;
        cpasync16(abase + (unsigned)(r * 144 + c8 * 16),
                  keysB + (size_t)(m0 + r) * ND + k0 + c8 * 4);
        cpasync16(bbase + (unsigned)(r * 144 + c8 * 16),
                  Wk + (size_t)(hc * 128 + r) * ND + k0 + c8 * 4);
    }
    asm volatile("cp.async.commit_group;" ::: "memory");
}

__global__ void __launch_bounds__(256, 2)
score_kernel(const float* __restrict__ keys,
             const float* __restrict__ Wk,
             const float* __restrict__ We,
             const int* __restrict__ lens,
             float* __restrict__ attn_out) {
    int b = blockIdx.y;
    int m0 = blockIdx.x * TM;
    int len = load_len(lens, b);
    if (m0 >= len) return;

    extern __shared__ float sm[];
    unsigned int sbase = smem_u32(sm);
    int tid = threadIdx.x, lane = tid & 31, wid = tid >> 5;
    int wm = wid >> 2, wn = wid & 3;
    const float* keysB = keys + (size_t)b * NM * ND;

    float d[4][4][4];
    float sp[4][2];
    #pragma unroll
    for (int mf = 0; mf < 4; ++mf) { sp[mf][0] = 0.f; sp[mf][1] = 0.f; }

    load_stage(sbase, keysB, Wk, m0, 0, tid);

    for (int s = 0; s < 256; ++s) {
        asm volatile("cp.async.wait_group 0;" ::: "memory");
        __syncthreads();
        if (s + 1 < 256) load_stage(sbase, keysB, Wk, m0, s + 1, tid);

        int bf = s & 1, kt = s & 31, hc = s >> 5;
        const float* As = sm + (bf * A_BYTES) / 4;
        const float* Bs = sm + (2 * A_BYTES + bf * A_BYTES) / 4;

        if (kt == 0) {
            #pragma unroll
            for (int mf = 0; mf < 4; ++mf)
                #pragma unroll
                for (int nf = 0; nf < 4; ++nf)
                    #pragma unroll
                    for (int e = 0; e < 4; ++e) d[mf][nf][e] = 0.f;
        }

        #pragma unroll
        for (int ks = 0; ks < 4; ++ks) {
            int c0 = ks * 8 + (lane & 3);
            unsigned int ua[4][4], ub[4][2];
            #pragma unroll
            for (int mf = 0; mf < 4; ++mf) {
                const float* Ab = As + (wm * 64 + mf * 16 + (lane >> 2)) * 36 + c0;
                ua[mf][0] = to_tf32(Ab[0]);
                ua[mf][1] = to_tf32(Ab[8 * 36]);
                ua[mf][2] = to_tf32(Ab[4]);
                ua[mf][3] = to_tf32(Ab[8 * 36 + 4]);
            }
            #pragma unroll
            for (int nf = 0; nf < 4; ++nf) {
                const float* Bb = Bs + (wn * 32 + nf * 8 + (lane >> 2)) * 36 + c0;
                ub[nf][0] = to_tf32(Bb[0]);
                ub[nf][1] = to_tf32(Bb[4]);
            }
            #pragma unroll
            for (int mf = 0; mf < 4; ++mf)
                #pragma unroll
                for (int nf = 0; nf < 4; ++nf)
                    mma_tf32(d[mf][nf], ua[mf], ub[nf]);
        }

        if (kt == 31) {
            // epilogue for this h-chunk: tanh(qp + pk) . W_energy
            float qv[4][2], we[4][2];
            int hbase = hc * 128 + wn * 32 + 2 * (lane & 3);
            #pragma unroll
            for (int nf = 0; nf < 4; ++nf) {
                #pragma unroll
                for (int p = 0; p < 2; ++p) {
                    qv[nf][p] = __ldg(&g_qp[b * ND + hbase + nf * 8 + p]);
                    we[nf][p] = __ldg(&We[hbase + nf * 8 + p]);
                }
            }
            #pragma unroll
            for (int mf = 0; mf < 4; ++mf)
                #pragma unroll
                for (int nf = 0; nf < 4; ++nf)
                    #pragma unroll
                    for (int e = 0; e < 4; ++e) {
                        float t = tanh_fast(d[mf][nf][e] + qv[nf][e & 1]);
                        sp[mf][e >> 1] += t * we[nf][e & 1];
                    }
        }
    }

    // cross-lane reduction of per-row partial scores via smem [128][17]
    __syncthreads();
    float* sred = sm;
    int col = wn * 4 + (lane & 3);
    #pragma unroll
    for (int mf = 0; mf < 4; ++mf)
        #pragma unroll
        for (int rb = 0; rb < 2; ++rb) {
            int r = wm * 64 + mf * 16 + (lane >> 2) + 8 * rb;
            sred[r * 17 + col] = sp[mf][rb];
        }
    __syncthreads();
    if (tid < 128) {
        float s = 0.f;
        #pragma unroll
        for (int j = 0; j < 16; ++j) s += sred[tid * 17 + j];
        attn_out[(size_t)b * NM + m0 + tid] = s;
    }
}

// ---------------- Kernel 3: masked softmax (in-place) --------------------
__global__ void softmax_kernel(const int* __restrict__ lens,
                               float* __restrict__ attn) {
    int b = blockIdx.x;
    int len = load_len(lens, b);
    float* row = attn + (size_t)b * NM;
    __shared__ float red[256];
    int tid = threadIdx.x;

    float mx = -3.0e38f;
    for (int m = tid; m < len; m += 256) mx = fmaxf(mx, row[m]);
    red[tid] = mx; __syncthreads();
    for (int s = 128; s; s >>= 1) {
        if (tid < s) red[tid] = fmaxf(red[tid], red[tid + s]);
        __syncthreads();
    }
    mx = red[0]; __syncthreads();

    float sm = 0.f;
    for (int m = tid; m < len; m += 256) sm += expf(row[m] - mx);
    red[tid] = sm; __syncthreads();
    for (int s = 128; s; s >>= 1) {
        if (tid < s) red[tid] += red[tid + s];
        __syncthreads();
    }
    float inv = 1.f / red[0];
    __syncthreads();

    for (int m = tid; m < NM; m += 256) {
        float w = (m < len) ? expf(row[m] - mx) * inv : 0.f;
        row[m] = w;
    }
}

// ---------------- Kernel 4: ctx partials (8 m-chunks per batch) ----------
__global__ void ctx_kernel(const float* __restrict__ values,
                           const int* __restrict__ lens,
                           const float* __restrict__ attn) {
    int b = blockIdx.y >> 3;
    int p = blockIdx.y & 7;
    int d = blockIdx.x * 256 + threadIdx.x;
    int len = load_len(lens, b);
    int mstart = p * 256;
    int mend = min(mstart + 256, len);

    __shared__ float sw[256];
    float acc = 0.f;
    if (mstart < mend) {
        int mm = mstart + threadIdx.x;
        sw[threadIdx.x] = (mm < mend) ? attn[(size_t)b * NM + mm] : 0.f;
        __syncthreads();
        const float* vb = values + (size_t)b * NM * ND;
        int lim = mend - mstart;
        #pragma unroll 8
        for (int t = 0; t < lim; ++t)
            acc += sw[t] * vb[(size_t)(mstart + t) * ND + d];
    }
    g_ctxp[((size_t)b * 8 + p) * ND + d] = acc;
}

// ---------------- Kernel 5: reduce partials ------------------------------
__global__ void reduce_ctx_kernel() {
    int b = blockIdx.x;
    for (int d = threadIdx.x; d < ND; d += 256) {
        float s = 0.f;
        #pragma unroll
        for (int p = 0; p < 8; ++p) s += g_ctxp[((size_t)b * 8 + p) * ND + d];
        g_ctx[b * ND + d] = s;
    }
}

// ---------------- Kernel 6: output projection ----------------------------
__global__ void outproj_kernel(const float* __restrict__ Wk,
                               float* __restrict__ out) {
    int b = blockIdx.y;
    int h = blockIdx.x * 8 + (threadIdx.x >> 5);
    int lane = threadIdx.x & 31;
    const float* xr = g_ctx + (size_t)b * ND;
    const float* wr = Wk + (size_t)h * ND;
    float acc = 0.f;
    #pragma unroll 8
    for (int d = lane; d < ND; d += 32) acc += xr[d] * wr[d];
    #pragma unroll
    for (int o = 16; o; o >>= 1) acc += __shfl_down_sync(0xffffffffu, acc, o);
    if (lane == 0) out[b * ND + h] = acc;
}

// ---------------- launch -------------------------------------------------
extern "C" void kernel_launch(void* const* d_in, const int* in_sizes, int n_in,
                              void* d_out, int out_size) {
    const float* queries = (const float*)d_in[0];
    const float* keys    = (const float*)d_in[1];
    const float* values  = (const float*)d_in[2];
    const int*   lens    = (const int*)d_in[3];
    const float* Wk      = (const float*)d_in[4];
    const float* Wq      = (const float*)d_in[5];
    const float* We      = (const float*)d_in[6];

    float* out      = (float*)d_out;
    float* out_val  = out;             // [B,1,D]
    float* out_attn = out + NB * ND;   // [B,1,M]

    static bool attr_set = false;
    if (!attr_set) {
        cudaFuncSetAttribute(score_kernel,
                             cudaFuncAttributeMaxDynamicSharedMemorySize, SC_SMEM);
        attr_set = true;
    }

    qproj_kernel  <<<dim3(ND / 8, NB), 256>>>(queries, Wq);
    score_kernel  <<<dim3(NM / TM, NB), 256, SC_SMEM>>>(keys, Wk, We, lens, out_attn);
    softmax_kernel<<<NB, 256>>>(lens, out_attn);
    ctx_kernel    <<<dim3(ND / 256, NB * 8), 256>>>(values, lens, out_attn);
    reduce_ctx_kernel<<<NB, 256>>>();
    outproj_kernel<<<dim3(ND / 8, NB), 256>>>(Wk, out_val);
}

// round 9
// speedup vs baseline: 3.4911x; 1.0460x over previous
#include <cuda_runtime.h>
#include <cstdint>

#define NB 32
#define NM 2048
#define ND 1024
#define TM 256               // score m-tile
#define A_BYTES 36864        // 256 rows * 36 floats * 4B
#define B_BYTES 18432        // 128 rows * 36 floats * 4B
#define SC_SMEM (2 * A_BYTES + 2 * B_BYTES)   // 110592

// scratch
__device__ float g_qp[NB * ND];
__device__ float g_ctx[NB * ND];
__device__ float g_ctxp[NB * 16 * ND];

// ---------------- helpers ------------------------------------------------
__device__ __forceinline__ int load_len(const int* __restrict__ L, int b) {
    bool is64 = (L[1] == 0) && (L[3] == 0) && (L[5] == 0);
    return is64 ? L[2 * b] : L[b];
}
__device__ __forceinline__ float tanh_fast(float x) {
    float r; asm("tanh.approx.f32 %0, %1;" : "=f"(r) : "f"(x)); return r;
}
__device__ __forceinline__ unsigned int smem_u32(const void* p) {
    unsigned int a;
    asm("{ .reg .u64 t; cvta.to.shared.u64 t, %1; cvt.u32.u64 %0, t; }" : "=r"(a) : "l"(p));
    return a;
}
__device__ __forceinline__ void cpasync16(unsigned int dst, const float* src) {
    asm volatile("cp.async.cg.shared.global [%0], [%1], 16;" :: "r"(dst), "l"(src) : "memory");
}
__device__ __forceinline__ unsigned int to_tf32(float x) {
    unsigned int u;
    asm("cvt.rna.tf32.f32 %0, %1;" : "=r"(u) : "f"(x));
    return u;
}
__device__ __forceinline__ void mma_tf32(float d[4], const unsigned int a[4],
                                         const unsigned int b[2]) {
    asm volatile(
        "mma.sync.aligned.m16n8k8.row.col.f32.tf32.tf32.f32 "
        "{%0,%1,%2,%3}, {%4,%5,%6,%7}, {%8,%9}, {%0,%1,%2,%3};"
        : "+f"(d[0]), "+f"(d[1]), "+f"(d[2]), "+f"(d[3])
        : "r"(a[0]), "r"(a[1]), "r"(a[2]), "r"(a[3]), "r"(b[0]), "r"(b[1]));
}

// ---------------- Kernel 1: q projection ---------------------------------
__global__ void qproj_kernel(const float* __restrict__ q,
                             const float* __restrict__ Wq) {
    int b = blockIdx.y;
    int h = blockIdx.x * 8 + (threadIdx.x >> 5);
    int lane = threadIdx.x & 31;
    const float* qr = q + (size_t)b * ND;
    const float* wr = Wq + (size_t)h * ND;
    float acc = 0.f;
    #pragma unroll 8
    for (int d = lane; d < ND; d += 32) acc += qr[d] * wr[d];
    #pragma unroll
    for (int o = 16; o; o >>= 1) acc += __shfl_down_sync(0xffffffffu, acc, o);
    if (lane == 0) g_qp[b * ND + h] = acc;
}

// ---------------- Kernel 2: tf32 mma.sync score GEMM ---------------------
// 256m x 128h CTA tile, 8 warps as 4(m) x 2(h), warp tile 64x64.
// Stage s = hc*32 + kt : A = keys[m0:m0+256, kt*32:+32], B = Wk[hc*128:+128, kt*32:+32]
__device__ __forceinline__ void load_stage(unsigned int sbase,
                                           const float* __restrict__ keysB,
                                           const float* __restrict__ Wk,
                                           int m0, int s, int tid) {
    int hc = s >> 5, kt = s & 31, bf = s & 1;
    int k0 = kt * 32;
    unsigned int abase = sbase + bf * A_BYTES;
    unsigned int bbase = sbase + 2 * A_BYTES + bf * B_BYTES;
    #pragma unroll
    for (int i = 0; i < 8; ++i) {
        int idx = i * 256 + tid;
        int r = idx >> 3, c8 = idx & 7;
        cpasync16(abase + (unsigned)(r * 144 + c8 * 16),
                  keysB + (size_t)(m0 + r) * ND + k0 + c8 * 4);
    }
    #pragma unroll
    for (int i = 0; i < 4; ++i) {
        int idx = i * 256 + tid;
        int r = idx >> 3, c8 = idx & 7;
        cpasync16(bbase + (unsigned)(r * 144 + c8 * 16),
                  Wk + (size_t)(hc * 128 + r) * ND + k0 + c8 * 4);
    }
    asm volatile("cp.async.commit_group;" ::: "memory");
}

__global__ void __launch_bounds__(256, 1)
score_kernel(const float* __restrict__ keys,
             const float* __restrict__ Wk,
             const float* __restrict__ We,
             const int* __restrict__ lens,
             float* __restrict__ attn_out) {
    int b = blockIdx.y;
    int m0 = blockIdx.x * TM;
    int len = load_len(lens, b);
    if (m0 >= len) return;

    extern __shared__ float sm[];
    unsigned int sbase = smem_u32(sm);
    int tid = threadIdx.x, lane = tid & 31, wid = tid >> 5;
    int wm = wid >> 1, wn = wid & 1;
    const float* keysB = keys + (size_t)b * NM * ND;

    float d[4][8][4];          // 128 accumulators: mf x nf x frag
    float sp[4][2];
    #pragma unroll
    for (int mf = 0; mf < 4; ++mf) { sp[mf][0] = 0.f; sp[mf][1] = 0.f; }

    load_stage(sbase, keysB, Wk, m0, 0, tid);

    for (int s = 0; s < 256; ++s) {
        asm volatile("cp.async.wait_group 0;" ::: "memory");
        __syncthreads();
        if (s + 1 < 256) load_stage(sbase, keysB, Wk, m0, s + 1, tid);

        int bf = s & 1, kt = s & 31, hc = s >> 5;
        const float* As = sm + (bf * A_BYTES) / 4;
        const float* Bs = sm + (2 * A_BYTES + bf * B_BYTES) / 4;

        if (kt == 0) {
            #pragma unroll
            for (int mf = 0; mf < 4; ++mf)
                #pragma unroll
                for (int nf = 0; nf < 8; ++nf)
                    #pragma unroll
                    for (int e = 0; e < 4; ++e) d[mf][nf][e] = 0.f;
        }

        #pragma unroll
        for (int ks = 0; ks < 4; ++ks) {
            int c0 = ks * 8 + (lane & 3);
            unsigned int ua[4][4], ub[8][2];
            #pragma unroll
            for (int mf = 0; mf < 4; ++mf) {
                const float* Ab = As + (wm * 64 + mf * 16 + (lane >> 2)) * 36 + c0;
                ua[mf][0] = to_tf32(Ab[0]);
                ua[mf][1] = to_tf32(Ab[8 * 36]);
                ua[mf][2] = to_tf32(Ab[4]);
                ua[mf][3] = to_tf32(Ab[8 * 36 + 4]);
            }
            #pragma unroll
            for (int nf = 0; nf < 8; ++nf) {
                const float* Bb = Bs + (wn * 64 + nf * 8 + (lane >> 2)) * 36 + c0;
                ub[nf][0] = to_tf32(Bb[0]);
                ub[nf][1] = to_tf32(Bb[4]);
            }
            #pragma unroll
            for (int mf = 0; mf < 4; ++mf)
                #pragma unroll
                for (int nf = 0; nf < 8; ++nf)
                    mma_tf32(d[mf][nf], ua[mf], ub[nf]);
        }

        if (kt == 31) {
            // epilogue for this h-chunk: tanh(qp + pk) . W_energy
            int hbase = hc * 128 + wn * 64 + 2 * (lane & 3);
            #pragma unroll
            for (int nf = 0; nf < 8; ++nf) {
                float qv0 = __ldg(&g_qp[b * ND + hbase + nf * 8]);
                float qv1 = __ldg(&g_qp[b * ND + hbase + nf * 8 + 1]);
                float we0 = __ldg(&We[hbase + nf * 8]);
                float we1 = __ldg(&We[hbase + nf * 8 + 1]);
                #pragma unroll
                for (int mf = 0; mf < 4; ++mf) {
                    sp[mf][0] += tanh_fast(d[mf][nf][0] + qv0) * we0;
                    sp[mf][0] += tanh_fast(d[mf][nf][1] + qv1) * we1;
                    sp[mf][1] += tanh_fast(d[mf][nf][2] + qv0) * we0;
                    sp[mf][1] += tanh_fast(d[mf][nf][3] + qv1) * we1;
                }
            }
        }
    }

    // cross-lane reduction of per-row partial scores via smem [256][9]
    __syncthreads();
    float* sred = sm;
    int col = wn * 4 + (lane & 3);
    #pragma unroll
    for (int mf = 0; mf < 4; ++mf)
        #pragma unroll
        for (int rb = 0; rb < 2; ++rb) {
            int r = wm * 64 + mf * 16 + (lane >> 2) + 8 * rb;
            sred[r * 9 + col] = sp[mf][rb];
        }
    __syncthreads();
    {
        float s = 0.f;
        #pragma unroll
        for (int j = 0; j < 8; ++j) s += sred[tid * 9 + j];
        attn_out[(size_t)b * NM + m0 + tid] = s;
    }
}

// ---------------- Kernel 3: masked softmax (in-place) --------------------
__global__ void softmax_kernel(const int* __restrict__ lens,
                               float* __restrict__ attn) {
    int b = blockIdx.x;
    int len = load_len(lens, b);
    float* row = attn + (size_t)b * NM;
    __shared__ float red[256];
    int tid = threadIdx.x;

    float mx = -3.0e38f;
    for (int m = tid; m < len; m += 256) mx = fmaxf(mx, row[m]);
    red[tid] = mx; __syncthreads();
    for (int s = 128; s; s >>= 1) {
        if (tid < s) red[tid] = fmaxf(red[tid], red[tid + s]);
        __syncthreads();
    }
    mx = red[0]; __syncthreads();

    float sm = 0.f;
    for (int m = tid; m < len; m += 256) sm += expf(row[m] - mx);
    red[tid] = sm; __syncthreads();
    for (int s = 128; s; s >>= 1) {
        if (tid < s) red[tid] += red[tid + s];
        __syncthreads();
    }
    float inv = 1.f / red[0];
    __syncthreads();

    for (int m = tid; m < NM; m += 256) {
        float w = (m < len) ? expf(row[m] - mx) * inv : 0.f;
        row[m] = w;
    }
}

// ---------------- Kernel 4: ctx partials (16 chunks x 128 rows, float4) --
__global__ void ctx_kernel(const float* __restrict__ values,
                           const int* __restrict__ lens,
                           const float* __restrict__ attn) {
    int b = blockIdx.x >> 4;
    int p = blockIdx.x & 15;
    int len = load_len(lens, b);
    int mstart = p * 128;
    int mend = min(mstart + 128, len);
    int tid = threadIdx.x;

    __shared__ float sw[128];
    float4 acc = make_float4(0.f, 0.f, 0.f, 0.f);
    if (mstart < mend) {
        if (tid < 128) {
            int mm = mstart + tid;
            sw[tid] = (mm < mend) ? attn[(size_t)b * NM + mm] : 0.f;
        }
        __syncthreads();
        const float4* vb4 = (const float4*)(values + (size_t)b * NM * ND);
        int lim = mend - mstart;
        #pragma unroll 4
        for (int t = 0; t < lim; ++t) {
            float w = sw[t];
            float4 v = __ldg(&vb4[(size_t)(mstart + t) * (ND / 4) + tid]);
            acc.x += w * v.x; acc.y += w * v.y;
            acc.z += w * v.z; acc.w += w * v.w;
        }
    }
    ((float4*)g_ctxp)[((size_t)b * 16 + p) * (ND / 4) + tid] = acc;
}

// ---------------- Kernel 5: reduce partials ------------------------------
__global__ void reduce_ctx_kernel() {
    int b = blockIdx.x;
    int d = threadIdx.x;
    float4 s = make_float4(0.f, 0.f, 0.f, 0.f);
    #pragma unroll
    for (int p = 0; p < 16; ++p) {
        float4 v = ((const float4*)g_ctxp)[((size_t)b * 16 + p) * (ND / 4) + d];
        s.x += v.x; s.y += v.y; s.z += v.z; s.w += v.w;
    }
    ((float4*)g_ctx)[(size_t)b * (ND / 4) + d] = s;
}

// ---------------- Kernel 6: output projection ----------------------------
__global__ void outproj_kernel(const float* __restrict__ Wk,
                               float* __restrict__ out) {
    int b = blockIdx.y;
    int h = blockIdx.x * 8 + (threadIdx.x >> 5);
    int lane = threadIdx.x & 31;
    const float* xr = g_ctx + (size_t)b * ND;
    const float* wr = Wk + (size_t)h * ND;
    float acc = 0.f;
    #pragma unroll 8
    for (int d = lane; d < ND; d += 32) acc += xr[d] * wr[d];
    #pragma unroll
    for (int o = 16; o; o >>= 1) acc += __shfl_down_sync(0xffffffffu, acc, o);
    if (lane == 0) out[b * ND + h] = acc;
}

// ---------------- launch -------------------------------------------------
extern "C" void kernel_launch(void* const* d_in, const int* in_sizes, int n_in,
                              void* d_out, int out_size) {
    const float* queries = (const float*)d_in[0];
    const float* keys    = (const float*)d_in[1];
    const float* values  = (const float*)d_in[2];
    const int*   lens    = (const int*)d_in[3];
    const float* Wk      = (const float*)d_in[4];
    const float* Wq      = (const float*)d_in[5];
    const float* We      = (const float*)d_in[6];

    float* out      = (float*)d_out;
    float* out_val  = out;             // [B,1,D]
    float* out_attn = out + NB * ND;   // [B,1,M]

    static bool attr_set = false;
    if (!attr_set) {
        cudaFuncSetAttribute(score_kernel,
                             cudaFuncAttributeMaxDynamicSharedMemorySize, SC_SMEM);
        attr_set = true;
    }

    qproj_kernel  <<<dim3(ND / 8, NB), 256>>>(queries, Wq);
    score_kernel  <<<dim3(NM / TM, NB), 256, SC_SMEM>>>(keys, Wk, We, lens, out_attn);
    softmax_kernel<<<NB, 256>>>(lens, out_attn);
    ctx_kernel    <<<NB * 16, 256>>>(values, lens, out_attn);
    reduce_ctx_kernel<<<NB, 256>>>();
    outproj_kernel<<<dim3(ND / 8, NB), 256>>>(Wk, out_val);
}

// round 10
// speedup vs baseline: 4.3354x; 1.2419x over previous
#include <cuda_runtime.h>
#include <cuda_bf16.h>
#include <cstdint>

#define NB 32
#define NM 2048
#define ND 1024
#define TM 256               // score m-tile
#define TH 128               // score h-tile
#define KE 64                // k elems per stage
#define NS 128               // stages = (ND/KE) * (ND/TH)
#define STRH 72              // smem row stride in halves (144B) -> conflict-free
#define A_ST (256 * STRH * 2)            // 36864
#define B_ST (128 * STRH * 2)            // 18432
#define STG (A_ST + B_ST)                // 55296
#define SC_SMEM (3 * STG)                // 165888

// scratch
__device__ float g_qp[NB * ND];
__device__ float g_ctx[NB * ND];
__device__ float g_ctxp[NB * 32 * ND];
__device__ __nv_bfloat16 g_kbf[(size_t)NB * NM * ND];   // keys in bf16
__device__ __nv_bfloat16 g_wkbf[ND * ND];               // W_key in bf16

// ---------------- helpers ------------------------------------------------
__device__ __forceinline__ int load_len(const int* __restrict__ L, int b) {
    bool is64 = (L[1] == 0) && (L[3] == 0) && (L[5] == 0);
    return is64 ? L[2 * b] : L[b];
}
__device__ __forceinline__ float tanh_fast(float x) {
    float r; asm("tanh.approx.f32 %0, %1;" : "=f"(r) : "f"(x)); return r;
}
__device__ __forceinline__ unsigned int smem_u32(const void* p) {
    unsigned int a;
    asm("{ .reg .u64 t; cvta.to.shared.u64 t, %1; cvt.u32.u64 %0, t; }" : "=r"(a) : "l"(p));
    return a;
}
__device__ __forceinline__ void cpasync16(unsigned int dst, const void* src) {
    asm volatile("cp.async.cg.shared.global [%0], [%1], 16;" :: "r"(dst), "l"(src) : "memory");
}
__device__ __forceinline__ void mma_bf16(float d[4], const unsigned int a[4],
                                         const unsigned int b[2]) {
    asm volatile(
        "mma.sync.aligned.m16n8k16.row.col.f32.bf16.bf16.f32 "
        "{%0,%1,%2,%3}, {%4,%5,%6,%7}, {%8,%9}, {%0,%1,%2,%3};"
        : "+f"(d[0]), "+f"(d[1]), "+f"(d[2]), "+f"(d[3])
        : "r"(a[0]), "r"(a[1]), "r"(a[2]), "r"(a[3]), "r"(b[0]), "r"(b[1]));
}

// ---------------- Kernel 0: fp32 -> bf16 conversion ----------------------
__global__ void conv_kernel(const float* __restrict__ src,
                            __nv_bfloat16* __restrict__ dst, int n8) {
    int i = blockIdx.x * blockDim.x + threadIdx.x;
    if (i >= n8) return;
    const float4* s4 = (const float4*)src;
    float4 a = __ldg(&s4[2 * i]);
    float4 b = __ldg(&s4[2 * i + 1]);
    __nv_bfloat162 p0 = __float22bfloat162_rn(make_float2(a.x, a.y));
    __nv_bfloat162 p1 = __float22bfloat162_rn(make_float2(a.z, a.w));
    __nv_bfloat162 p2 = __float22bfloat162_rn(make_float2(b.x, b.y));
    __nv_bfloat162 p3 = __float22bfloat162_rn(make_float2(b.z, b.w));
    uint4 o;
    o.x = *(unsigned int*)&p0; o.y = *(unsigned int*)&p1;
    o.z = *(unsigned int*)&p2; o.w = *(unsigned int*)&p3;
    ((uint4*)dst)[i] = o;
}

// ---------------- Kernel 1: q projection (Wq read once) ------------------
__global__ void qproj_kernel(const float* __restrict__ q,
                             const float* __restrict__ Wq) {
    int h = blockIdx.x * 8 + (threadIdx.x >> 5);
    int lane = threadIdx.x & 31;
    float wq[32];
    const float* wr = Wq + (size_t)h * ND;
    #pragma unroll
    for (int j = 0; j < 32; ++j) wq[j] = __ldg(&wr[lane + 32 * j]);
    for (int b = 0; b < NB; ++b) {
        const float* qr = q + (size_t)b * ND;
        float acc = 0.f;
        #pragma unroll
        for (int j = 0; j < 32; ++j) acc += __ldg(&qr[lane + 32 * j]) * wq[j];
        #pragma unroll
        for (int o = 16; o; o >>= 1) acc += __shfl_down_sync(0xffffffffu, acc, o);
        if (lane == 0) g_qp[b * ND + h] = acc;
    }
}

// ---------------- Kernel 2: bf16 mma.sync score GEMM ---------------------
// 256m x 128h CTA tile, warps 4(m) x 2(h), warp tile 64x64, KE=64/stage,
// 3-deep cp.async ring. scores = sum_h We[h]*tanh(qp[b,h]+keys.Wk^T)
__device__ __forceinline__ void load_stage(unsigned int sbase,
                                           const __nv_bfloat16* __restrict__ keysB,
                                           int m0, int s, int tid) {
    int hc = s >> 4, kt = s & 15, bf = s % 3;
    int k0 = kt * KE;
    unsigned int abase = sbase + bf * STG;
    unsigned int bbase = abase + A_ST;
    #pragma unroll
    for (int i = 0; i < 8; ++i) {
        int idx = i * 256 + tid;
        int r = idx >> 3, c = idx & 7;
        cpasync16(abase + (unsigned)(r * 144 + c * 16),
                  keysB + (size_t)(m0 + r) * ND + k0 + c * 8);
    }
    #pragma unroll
    for (int i = 0; i < 4; ++i) {
        int idx = i * 256 + tid;
        int r = idx >> 3, c = idx & 7;
        cpasync16(bbase + (unsigned)(r * 144 + c * 16),
                  g_wkbf + (size_t)(hc * 128 + r) * ND + k0 + c * 8);
    }
    asm volatile("cp.async.commit_group;" ::: "memory");
}

__global__ void __launch_bounds__(256, 1)
score_kernel(const float* __restrict__ We,
             const int* __restrict__ lens,
             float* __restrict__ attn_out) {
    int b = blockIdx.y;
    int m0 = blockIdx.x * TM;
    int len = load_len(lens, b);
    if (m0 >= len) return;

    extern __shared__ char smem[];
    unsigned int sbase = smem_u32(smem);
    int tid = threadIdx.x, lane = tid & 31, wid = tid >> 5;
    int wm = wid >> 1, wn = wid & 1;
    const __nv_bfloat16* keysB = g_kbf + (size_t)b * NM * ND;

    float d[4][8][4];
    float sp[4][2];
    #pragma unroll
    for (int mf = 0; mf < 4; ++mf) { sp[mf][0] = 0.f; sp[mf][1] = 0.f; }

    load_stage(sbase, keysB, m0, 0, tid);
    load_stage(sbase, keysB, m0, 1, tid);

    for (int s = 0; s < NS; ++s) {
        if (s + 2 < NS) asm volatile("cp.async.wait_group 1;" ::: "memory");
        else            asm volatile("cp.async.wait_group 0;" ::: "memory");
        __syncthreads();
        if (s + 2 < NS) load_stage(sbase, keysB, m0, s + 2, tid);

        int bf = s % 3, kt = s & 15, hc = s >> 4;
        const __nv_bfloat16* As = (const __nv_bfloat16*)(smem + bf * STG);
        const __nv_bfloat16* Bs = (const __nv_bfloat16*)(smem + bf * STG + A_ST);

        if (kt == 0) {
            #pragma unroll
            for (int mf = 0; mf < 4; ++mf)
                #pragma unroll
                for (int nf = 0; nf < 8; ++nf)
                    #pragma unroll
                    for (int e = 0; e < 4; ++e) d[mf][nf][e] = 0.f;
        }

        #pragma unroll
        for (int ks = 0; ks < 4; ++ks) {
            int c0 = ks * 16 + (lane & 3) * 2;
            unsigned int ua[4][4], ub[8][2];
            #pragma unroll
            for (int mf = 0; mf < 4; ++mf) {
                const __nv_bfloat16* Ab =
                    As + (wm * 64 + mf * 16 + (lane >> 2)) * STRH + c0;
                ua[mf][0] = *(const unsigned int*)(Ab);
                ua[mf][1] = *(const unsigned int*)(Ab + 8 * STRH);
                ua[mf][2] = *(const unsigned int*)(Ab + 8);
                ua[mf][3] = *(const unsigned int*)(Ab + 8 * STRH + 8);
            }
            #pragma unroll
            for (int nf = 0; nf < 8; ++nf) {
                const __nv_bfloat16* Bb =
                    Bs + (wn * 64 + nf * 8 + (lane >> 2)) * STRH + c0;
                ub[nf][0] = *(const unsigned int*)(Bb);
                ub[nf][1] = *(const unsigned int*)(Bb + 8);
            }
            #pragma unroll
            for (int mf = 0; mf < 4; ++mf)
                #pragma unroll
                for (int nf = 0; nf < 8; ++nf)
                    mma_bf16(d[mf][nf], ua[mf], ub[nf]);
        }

        if (kt == 15) {
            int hbase = hc * 128 + wn * 64 + 2 * (lane & 3);
            #pragma unroll
            for (int nf = 0; nf < 8; ++nf) {
                float qv0 = __ldg(&g_qp[b * ND + hbase + nf * 8]);
                float qv1 = __ldg(&g_qp[b * ND + hbase + nf * 8 + 1]);
                float we0 = __ldg(&We[hbase + nf * 8]);
                float we1 = __ldg(&We[hbase + nf * 8 + 1]);
                #pragma unroll
                for (int mf = 0; mf < 4; ++mf) {
                    sp[mf][0] += tanh_fast(d[mf][nf][0] + qv0) * we0;
                    sp[mf][0] += tanh_fast(d[mf][nf][1] + qv1) * we1;
                    sp[mf][1] += tanh_fast(d[mf][nf][2] + qv0) * we0;
                    sp[mf][1] += tanh_fast(d[mf][nf][3] + qv1) * we1;
                }
            }
        }
    }

    // cross-lane reduction via smem [256][9]
    __syncthreads();
    float* sred = (float*)smem;
    int col = wn * 4 + (lane & 3);
    #pragma unroll
    for (int mf = 0; mf < 4; ++mf)
        #pragma unroll
        for (int rb = 0; rb < 2; ++rb) {
            int r = wm * 64 + mf * 16 + (lane >> 2) + 8 * rb;
            sred[r * 9 + col] = sp[mf][rb];
        }
    __syncthreads();
    {
        float s = 0.f;
        #pragma unroll
        for (int j = 0; j < 8; ++j) s += sred[tid * 9 + j];
        attn_out[(size_t)b * NM + m0 + tid] = s;
    }
}

// ---------------- Kernel 3: masked softmax (in-place) --------------------
__global__ void softmax_kernel(const int* __restrict__ lens,
                               float* __restrict__ attn) {
    int b = blockIdx.x;
    int len = load_len(lens, b);
    float* row = attn + (size_t)b * NM;
    __shared__ float red[256];
    int tid = threadIdx.x;

    float mx = -3.0e38f;
    for (int m = tid; m < len; m += 256) mx = fmaxf(mx, row[m]);
    red[tid] = mx; __syncthreads();
    for (int s = 128; s; s >>= 1) {
        if (tid < s) red[tid] = fmaxf(red[tid], red[tid + s]);
        __syncthreads();
    }
    mx = red[0]; __syncthreads();

    float sm = 0.f;
    for (int m = tid; m < len; m += 256) sm += expf(row[m] - mx);
    red[tid] = sm; __syncthreads();
    for (int s = 128; s; s >>= 1) {
        if (tid < s) red[tid] += red[tid + s];
        __syncthreads();
    }
    float inv = 1.f / red[0];
    __syncthreads();

    for (int m = tid; m < NM; m += 256) {
        float w = (m < len) ? expf(row[m] - mx) * inv : 0.f;
        row[m] = w;
    }
}

// ---------------- Kernel 4: ctx partials (32 chunks x 64 rows, float4) ---
__global__ void ctx_kernel(const float* __restrict__ values,
                           const int* __restrict__ lens,
                           const float* __restrict__ attn) {
    int b = blockIdx.x >> 5;
    int p = blockIdx.x & 31;
    int len = load_len(lens, b);
    int mstart = p * 64;
    int mend = min(mstart + 64, len);
    int tid = threadIdx.x;

    __shared__ float sw[64];
    float4 acc = make_float4(0.f, 0.f, 0.f, 0.f);
    if (mstart < mend) {
        if (tid < 64) {
            int mm = mstart + tid;
            sw[tid] = (mm < mend) ? attn[(size_t)b * NM + mm] : 0.f;
        }
        __syncthreads();
        const float4* vb4 = (const float4*)(values + (size_t)b * NM * ND);
        int lim = mend - mstart;
        #pragma unroll 8
        for (int t = 0; t < lim; ++t) {
            float w = sw[t];
            float4 v = __ldg(&vb4[(size_t)(mstart + t) * (ND / 4) + tid]);
            acc.x += w * v.x; acc.y += w * v.y;
            acc.z += w * v.z; acc.w += w * v.w;
        }
    }
    ((float4*)g_ctxp)[((size_t)b * 32 + p) * (ND / 4) + tid] = acc;
}

// ---------------- Kernel 5: reduce partials ------------------------------
__global__ void reduce_ctx_kernel() {
    int b = blockIdx.x;
    int d = threadIdx.x;
    float4 s = make_float4(0.f, 0.f, 0.f, 0.f);
    #pragma unroll
    for (int p = 0; p < 32; ++p) {
        float4 v = ((const float4*)g_ctxp)[((size_t)b * 32 + p) * (ND / 4) + d];
        s.x += v.x; s.y += v.y; s.z += v.z; s.w += v.w;
    }
    ((float4*)g_ctx)[(size_t)b * (ND / 4) + d] = s;
}

// ---------------- Kernel 6: output projection (Wk read once) -------------
__global__ void outproj_kernel(const float* __restrict__ Wk,
                               float* __restrict__ out) {
    int h = blockIdx.x * 8 + (threadIdx.x >> 5);
    int lane = threadIdx.x & 31;
    float wk[32];
    const float* wr = Wk + (size_t)h * ND;
    #pragma unroll
    for (int j = 0; j < 32; ++j) wk[j] = __ldg(&wr[lane + 32 * j]);
    for (int b = 0; b < NB; ++b) {
        const float* xr = g_ctx + (size_t)b * ND;
        float acc = 0.f;
        #pragma unroll
        for (int j = 0; j < 32; ++j) acc += xr[lane + 32 * j] * wk[j];
        #pragma unroll
        for (int o = 16; o; o >>= 1) acc += __shfl_down_sync(0xffffffffu, acc, o);
        if (lane == 0) out[b * ND + h] = acc;
    }
}

// ---------------- launch -------------------------------------------------
extern "C" void kernel_launch(void* const* d_in, const int* in_sizes, int n_in,
                              void* d_out, int out_size) {
    const float* queries = (const float*)d_in[0];
    const float* keys    = (const float*)d_in[1];
    const float* values  = (const float*)d_in[2];
    const int*   lens    = (const int*)d_in[3];
    const float* Wk      = (const float*)d_in[4];
    const float* Wq      = (const float*)d_in[5];
    const float* We      = (const float*)d_in[6];

    float* out      = (float*)d_out;
    float* out_val  = out;             // [B,1,D]
    float* out_attn = out + NB * ND;   // [B,1,M]

    static bool attr_set = false;
    if (!attr_set) {
        cudaFuncSetAttribute(score_kernel,
                             cudaFuncAttributeMaxDynamicSharedMemorySize, SC_SMEM);
        attr_set = true;
    }

    __nv_bfloat16* kbf;  cudaGetSymbolAddress((void**)&kbf, g_kbf);
    __nv_bfloat16* wkbf; cudaGetSymbolAddress((void**)&wkbf, g_wkbf);

    conv_kernel   <<<(NB * NM * ND / 8 + 255) / 256, 256>>>(keys, kbf, NB * NM * ND / 8);
    conv_kernel   <<<(ND * ND / 8 + 255) / 256, 256>>>(Wk, wkbf, ND * ND / 8);
    qproj_kernel  <<<ND / 8, 256>>>(queries, Wq);
    score_kernel  <<<dim3(NM / TM, NB), 256, SC_SMEM>>>(We, lens, out_attn);
    softmax_kernel<<<NB, 256>>>(lens, out_attn);
    ctx_kernel    <<<NB * 32, 256>>>(values, lens, out_attn);
    reduce_ctx_kernel<<<NB, 256>>>();
    outproj_kernel<<<ND / 8, 256>>>(Wk, out_val);
}